// round 5
// baseline (speedup 1.0000x reference)
#include <cuda_runtime.h>
#include <cstdint>
#include <cstddef>

// Problem constants
#define T_TOKENS 65536
#define DM 2048
#define NE 64

// Tiling: 1-warp CTAs, 64 tokens/CTA, per-thread 16 tokens x 8 experts
#define KC 32
#define TCTA 64
#define THREADS 32

// Output layout (flattened tuple, all float32) — validated in R4:
//   [0, T*E)            one-hot
//   [T*E, T*E+T)        top_prob
//   [T*E+T, ...)        logits
#define TP_OFF ((size_t)T_TOKENS * NE)
#define LG_OFF ((size_t)T_TOKENS * NE + T_TOKENS)

typedef unsigned long long ull;

// ---- packed f32x2 helpers ----
__device__ __forceinline__ ull fma2(ull a, ull b, ull c) {
    ull d;
    asm("fma.rn.f32x2 %0, %1, %2, %3;" : "=l"(d) : "l"(a), "l"(b), "l"(c));
    return d;
}
__device__ __forceinline__ ull dup2(float w) {
    ull d;
    asm("mov.b64 %0, {%1, %1};" : "=l"(d) : "f"(w));
    return d;
}
__device__ __forceinline__ ull pack2(float lo, float hi) {
    ull d;
    asm("mov.b64 %0, {%1, %2};" : "=l"(d) : "f"(lo), "f"(hi));
    return d;
}
__device__ __forceinline__ float2 unpack2(ull u) {
    float2 f;
    asm("mov.b64 {%0, %1}, %2;" : "=f"(f.x), "=f"(f.y) : "l"(u));
    return f;
}

__global__ void __launch_bounds__(THREADS, 10)
router_kernel(const float* __restrict__ x,
              const float* __restrict__ W,
              float* __restrict__ out) {
    // xs: token-major, stride 36 (16B-aligned rows, bank offset 4i per token).
    // Element (t,k) stored at xs[t][k ^ (8*(t>>4))] -> conflict-free LDS.32
    // across the 4 ty-groups (XOR masks {0,8,16,24} hit distinct banks) and
    // conflict-free STS.128 fills (phase-mates share t, cover 128B).
    __shared__ __align__(16) float xs[TCTA][36];   // 9216 B
    // ws: k-major, stride 65 (65 == 1 mod 32) -> conflict-free scalar fills
    // and conflict-free compute loads ws[k][tx + 8j].
    __shared__ __align__(16) float ws[KC][65];     // 8320 B

    const int tid  = threadIdx.x;
    const int tx   = tid & 7;          // expert lane: owns e = tx + 8j
    const int tyq  = tid >> 3;         // token group: tokens tyq*16 .. +15
    const int t0   = blockIdx.x * TCTA;

    const int c4    = tx * 4;          // fill: column group (16B)
    const int cswz  = tyq << 3;        // xs column swizzle for this thread
    const int tbase = tyq * 16;

    // acc[p][j]: token pair (tbase+2p, tbase+2p+1) x expert (tx+8j)
    ull acc[8][8];
#pragma unroll
    for (int p = 0; p < 8; p++)
#pragma unroll
        for (int j = 0; j < 8; j++) acc[p][j] = 0ull;

    for (int k0 = 0; k0 < DM; k0 += KC) {
        __syncwarp();   // previous chunk's reads complete before overwrite

        // ---- fill xs: coalesced LDG.128 (4 rows x 128B per instr),
        //      swizzled STS.128 (conflict-free) ----
#pragma unroll
        for (int rr = 0; rr < 16; rr++) {
            const int r = tyq + 4 * rr;
            float4 v = *(const float4*)(x + (size_t)(t0 + r) * DM + k0 + c4);
            const int col = c4 ^ ((r >> 4) << 3);
            *(float4*)&xs[r][col] = v;
        }
        // ---- fill ws: coalesced LDG.128, transposed scalar STS
        //      (banks 4c+q+j+4rr -> conflict-free with stride 65) ----
#pragma unroll
        for (int rr = 0; rr < 16; rr++) {
            const int r = tyq + 4 * rr;   // expert row
            float4 v = *(const float4*)(W + (size_t)r * DM + k0 + c4);
            ws[c4 + 0][r] = v.x;
            ws[c4 + 1][r] = v.y;
            ws[c4 + 2][r] = v.z;
            ws[c4 + 3][r] = v.w;
        }
        __syncwarp();

        // ---- compute: per k, 24 LDS.32 (24 wf) + 64 FFMA2 (128 cyc) ----
#pragma unroll 8
        for (int kk = 0; kk < KC; kk++) {
            const int kx = kk ^ cswz;
            ull xp[8];
#pragma unroll
            for (int p = 0; p < 8; p++)
                xp[p] = pack2(xs[tbase + 2 * p][kx], xs[tbase + 2 * p + 1][kx]);
            ull wd[8];
#pragma unroll
            for (int j = 0; j < 8; j++) wd[j] = dup2(ws[kk][tx + 8 * j]);
#pragma unroll
            for (int p = 0; p < 8; p++)
#pragma unroll
                for (int j = 0; j < 8; j++)
                    acc[p][j] = fma2(xp[p], wd[j], acc[p][j]);
        }
    }

    // ---- epilogue: softmax/argmax per token over 8 tx-lanes ----
#pragma unroll
    for (int p = 0; p < 8; p++) {
        float la[2][8];
#pragma unroll
        for (int j = 0; j < 8; j++) {
            float2 f = unpack2(acc[p][j]);
            la[0][j] = f.x;
            la[1][j] = f.y;
        }
#pragma unroll
        for (int a = 0; a < 2; a++) {
            const int t = t0 + tbase + 2 * p + a;

            // local argmax (expert ids tx+8j strictly increase with j ->
            // strict '>' keeps the FIRST max, matching jnp.argmax)
            float m = la[a][0];
            int   e = tx;
#pragma unroll
            for (int j = 1; j < 8; j++) {
                const int ej = tx + 8 * j;
                if (la[a][j] > m) { m = la[a][j]; e = ej; }
            }
            // butterfly over the 8-lane tx group (lanes tid = tx + 8*tyq)
#pragma unroll
            for (int msk = 1; msk < 8; msk <<= 1) {
                float om = __shfl_xor_sync(0xffffffffu, m, msk);
                int   oe = __shfl_xor_sync(0xffffffffu, e, msk);
                if (om > m || (om == m && oe < e)) { m = om; e = oe; }
            }

            float s = 0.f;
#pragma unroll
            for (int j = 0; j < 8; j++) s += __expf(la[a][j] - m);
#pragma unroll
            for (int msk = 1; msk < 8; msk <<= 1)
                s += __shfl_xor_sync(0xffffffffu, s, msk);

            float* lg = out + LG_OFF + (size_t)t * NE;
            float* oh = out + (size_t)t * NE;
#pragma unroll
            for (int j = 0; j < 8; j++) {
                const int ej = tx + 8 * j;
                lg[ej] = la[a][j];
                oh[ej] = (ej == e) ? 1.f : 0.f;
            }
            if (tx == 0) out[TP_OFF + t] = 1.0f / s;
        }
    }
}

extern "C" void kernel_launch(void* const* d_in, const int* in_sizes, int n_in,
                              void* d_out, int out_size) {
    const float* x = (const float*)d_in[0];   // [65536, 2048] f32
    const float* W = (const float*)d_in[1];   // [64, 2048] f32
    float* out = (float*)d_out;

    dim3 grid(T_TOKENS / TCTA);   // 1024 one-warp CTAs
    dim3 block(THREADS);
    router_kernel<<<grid, block>>>(x, W, out);
}

// round 6
// speedup vs baseline: 1.3380x; 1.3380x over previous
#include <cuda_runtime.h>
#include <cstdint>
#include <cstddef>

// Problem constants
#define T_TOKENS 65536
#define DM 2048
#define NE 64

// Tiling: 1-warp CTAs, 64 tokens/CTA, per-thread 16 tokens x 8 experts.
// KC=16 k-chunk, register-double-buffered global->smem pipeline.
#define KC 16
#define TCTA 64
#define NCHUNK (DM / KC)   // 128

// Output layout (flattened tuple, all float32) — validated R4/R5:
#define TP_OFF ((size_t)T_TOKENS * NE)
#define LG_OFF ((size_t)T_TOKENS * NE + T_TOKENS)

typedef unsigned long long ull;

__device__ __forceinline__ ull fma2(ull a, ull b, ull c) {
    ull d;
    asm("fma.rn.f32x2 %0, %1, %2, %3;" : "=l"(d) : "l"(a), "l"(b), "l"(c));
    return d;
}
__device__ __forceinline__ ull dup2(float w) {
    ull d;
    asm("mov.b64 %0, {%1, %1};" : "=l"(d) : "f"(w));
    return d;
}
__device__ __forceinline__ ull pack2(float lo, float hi) {
    ull d;
    asm("mov.b64 %0, {%1, %2};" : "=l"(d) : "f"(lo), "f"(hi));
    return d;
}
__device__ __forceinline__ float2 unpack2(ull u) {
    float2 f;
    asm("mov.b64 {%0, %1}, %2;" : "=f"(f.x), "=f"(f.y) : "l"(u));
    return f;
}

__global__ void __launch_bounds__(32)
router_kernel(const float* __restrict__ x,
              const float* __restrict__ W,
              float* __restrict__ out) {
    // xs[t][k ^ 4*((t>>4)&3)], stride 20: conflict-free STS.128 fills and
    // conflict-free compute LDS.32 (banks 8p + (k^4q) distinct over q).
    __shared__ __align__(16) float xs[TCTA][20];   // 5120 B
    // ws[e][k], stride 20: compute load ws[tx+8j][k] -> banks 20e+k ==
    // 20*tx + k (mod 32), distinct over tx. Fill is straight STS.128.
    __shared__ __align__(16) float ws[NE][20];     // 5120 B

    const int lane = threadIdx.x;
    const int tx   = lane & 7;        // expert lane: e = tx + 8j
    const int tyq  = lane >> 3;       // token group: tokens tyq*16 .. +15
    const int fa   = lane >> 2;       // fill: row sub-index 0..7
    const int fc   = (lane & 3) * 4;  // fill: col (floats) 0/4/8/12
    const int t0   = blockIdx.x * TCTA;
    const int tbase = tyq * 16;
    const int cswz  = tyq << 2;       // compute-side column swizzle

    // acc[p][j]: token pair (tbase+2p, tbase+2p+1) x expert (tx+8j)
    ull acc[8][8];
#pragma unroll
    for (int p = 0; p < 8; p++)
#pragma unroll
        for (int j = 0; j < 8; j++) acc[p][j] = 0ull;

    // Prefetch registers for the global->smem pipeline (chunk c+1)
    float4 xf[8], wf[8];

    // prologue: load chunk 0
#pragma unroll
    for (int rr = 0; rr < 8; rr++) {
        const int r = fa + 8 * rr;
        xf[rr] = *(const float4*)(x + (size_t)(t0 + r) * DM + fc);
        wf[rr] = *(const float4*)(W + (size_t)r * DM + fc);
    }

    for (int c = 0; c < NCHUNK; c++) {
        __syncwarp();   // previous chunk's LDS reads done before overwrite

        // ---- store prefetched chunk c into smem ----
#pragma unroll
        for (int rr = 0; rr < 8; rr++) {
            const int r = fa + 8 * rr;
            const int xcol = fc ^ (((r >> 4) & 3) << 2);
            *(float4*)&xs[r][xcol] = xf[rr];
            *(float4*)&ws[r][fc]   = wf[rr];
        }
        __syncwarp();

        // ---- prefetch chunk c+1 (LDG overlaps the compute below) ----
        if (c + 1 < NCHUNK) {
            const int k0 = (c + 1) * KC;
#pragma unroll
            for (int rr = 0; rr < 8; rr++) {
                const int r = fa + 8 * rr;
                xf[rr] = *(const float4*)(x + (size_t)(t0 + r) * DM + k0 + fc);
                wf[rr] = *(const float4*)(W + (size_t)r * DM + k0 + fc);
            }
        }

        // ---- compute chunk c: per k, 24 LDS.32 (24 wf) + 64 FFMA2 ----
#pragma unroll
        for (int kk = 0; kk < KC; kk++) {
            const int kx = kk ^ cswz;
            ull xp[8];
#pragma unroll
            for (int p = 0; p < 8; p++)
                xp[p] = pack2(xs[tbase + 2 * p][kx], xs[tbase + 2 * p + 1][kx]);
            ull wd[8];
#pragma unroll
            for (int j = 0; j < 8; j++) wd[j] = dup2(ws[tx + 8 * j][kk]);
#pragma unroll
            for (int p = 0; p < 8; p++)
#pragma unroll
                for (int j = 0; j < 8; j++)
                    acc[p][j] = fma2(xp[p], wd[j], acc[p][j]);
        }
    }

    // ---- epilogue: softmax/argmax per token over the 8 tx-lanes ----
#pragma unroll
    for (int p = 0; p < 8; p++) {
        float la[2][8];
#pragma unroll
        for (int j = 0; j < 8; j++) {
            float2 f = unpack2(acc[p][j]);
            la[0][j] = f.x;
            la[1][j] = f.y;
        }
#pragma unroll
        for (int a = 0; a < 2; a++) {
            const int t = t0 + tbase + 2 * p + a;

            // local argmax; expert ids tx+8j strictly increase with j ->
            // strict '>' keeps the FIRST max (matches jnp.argmax)
            float m = la[a][0];
            int   e = tx;
#pragma unroll
            for (int j = 1; j < 8; j++) {
                const int ej = tx + 8 * j;
                if (la[a][j] > m) { m = la[a][j]; e = ej; }
            }
            // butterfly over the 8-lane tx group (lanes lane = tx + 8*tyq)
#pragma unroll
            for (int msk = 1; msk < 8; msk <<= 1) {
                float om = __shfl_xor_sync(0xffffffffu, m, msk);
                int   oe = __shfl_xor_sync(0xffffffffu, e, msk);
                if (om > m || (om == m && oe < e)) { m = om; e = oe; }
            }

            float s = 0.f;
#pragma unroll
            for (int j = 0; j < 8; j++) s += __expf(la[a][j] - m);
#pragma unroll
            for (int msk = 1; msk < 8; msk <<= 1)
                s += __shfl_xor_sync(0xffffffffu, s, msk);

            float* lg = out + LG_OFF + (size_t)t * NE;
            float* oh = out + (size_t)t * NE;
#pragma unroll
            for (int j = 0; j < 8; j++) {
                const int ej = tx + 8 * j;
                lg[ej] = la[a][j];
                oh[ej] = (ej == e) ? 1.f : 0.f;
            }
            if (tx == 0) out[TP_OFF + t] = 1.0f / s;
        }
    }
}

extern "C" void kernel_launch(void* const* d_in, const int* in_sizes, int n_in,
                              void* d_out, int out_size) {
    const float* x = (const float*)d_in[0];   // [65536, 2048] f32
    const float* W = (const float*)d_in[1];   // [64, 2048] f32
    float* out = (float*)d_out;

    dim3 grid(T_TOKENS / TCTA);   // 1024 one-warp CTAs
    dim3 block(32);
    router_kernel<<<grid, block>>>(x, W, out);
}